// round 3
// baseline (speedup 1.0000x reference)
#include <cuda_runtime.h>

// PrefixSumCounts: counts[b,s] = #{t <= s : x[b,t] == x[b,s]}
// B=4, S=4096, V=32000 (fixed by this problem instance).
//
// Single fused kernel, 64 blocks = B*C (all co-resident, grid < #SMs):
//  phase 1 (block-local): within-chunk inclusive rank via SMEM scan;
//           build a 512-slot SMEM hash {value+1, count} of this chunk's
//           values; dump ALL 512 slots (incl. zeros) to the global table.
//           Full overwrite each launch -> no pre-zero, no cleanup, and every
//           line phase 2 can probe is freshly written => L2-resident.
//  ONE grid barrier (dump visible everywhere).
//  phase 2: base = sum over earlier chunks cp<c of hash-probe(table[b][cp], v)
//           (15 independent short probe chains, all L2 hits).
//           out = rank + 1 + base.
//  tail: second arrival counter; its last arriver resets both counters to 0
//        (safe: reaching counter2 implies all blocks passed the counter1 spin).

#define BB 4
#define SS 4096
#define CC 16
#define LL 256             // SS / CC
#define NBLK (BB * CC)     // 64
#define HSLOTS 512         // per-chunk hash slots (>= 2x max distinct = 256)
#define HMASK (HSLOTS - 1)

__device__ int2 g_tab[NBLK * HSLOTS];  // 256 KB; fully overwritten each launch
__device__ unsigned int g_bar1;        // 0 at load; restored to 0 each launch
__device__ unsigned int g_bar2;

__device__ __forceinline__ unsigned int hash_v(int v) {
    return ((unsigned int)v * 2654435761u) >> 23;  // top 9 bits, & HMASK by caller
}

__global__ void __launch_bounds__(LL, 1) fused_counts_kernel(
    const int* __restrict__ x, float* __restrict__ out)
{
    __shared__ int xs[LL];
    __shared__ int sval[HSLOTS];
    __shared__ int scnt[HSLOTS];

    const int c = blockIdx.x & (CC - 1);
    const int b = blockIdx.x >> 4;
    const int t = threadIdx.x;
    const int gpos = b * SS + c * LL + t;

    // zero SMEM hash (4 slots per thread)
#pragma unroll
    for (int i = 0; i < HSLOTS / LL; ++i) {
        sval[t + i * LL] = 0;
        scnt[t + i * LL] = 0;
    }

    const int v = __ldg(&x[gpos]);
    xs[t] = v;
    __syncthreads();

    // ---- within-chunk inclusive rank (SMEM broadcast scan) ----
    int rank = 0;
#pragma unroll 4
    for (int j = 0; j < t; ++j) {
        rank += (xs[j] == v);
    }

    // ---- insert into SMEM hash: claim slot via CAS, count via atomicAdd ----
    {
        unsigned int h = hash_v(v) & HMASK;
        const int key = v + 1;
        while (true) {
            int old = atomicCAS(&sval[h], 0, key);
            if (old == 0 || old == key) { atomicAdd(&scnt[h], 1); break; }
            h = (h + 1) & HMASK;
        }
    }
    __syncthreads();

    // ---- dump full SMEM hash to global (all 512 slots -> L2-resident) ----
    int2* my_tab = &g_tab[blockIdx.x * HSLOTS];
#pragma unroll
    for (int i = 0; i < HSLOTS / LL; ++i) {
        int s = t + i * LL;
        my_tab[s] = make_int2(sval[s], scnt[s]);
    }

    // ---- grid barrier: all dumps visible ----
    __syncthreads();
    if (t == 0) {
        __threadfence();
        atomicAdd(&g_bar1, 1u);
        volatile unsigned int* p = &g_bar1;
        while (*p < NBLK) { }
        __threadfence();
    }
    __syncthreads();

    // ---- phase 2: probe earlier chunks' tables (independent L2 chains) ----
    const unsigned int h0 = hash_v(v) & HMASK;
    const int key = v + 1;
    const int2* row = &g_tab[(b * CC) * HSLOTS];
    int base = 0;
#pragma unroll
    for (int cp = 0; cp < CC - 1; ++cp) {
        if (cp < c) {
            const int2* tab = row + cp * HSLOTS;
            unsigned int h = h0;
            while (true) {
                int2 e = tab[h];
                if (e.x == key) { base += e.y; break; }
                if (e.x == 0) break;        // value absent in that chunk
                h = (h + 1) & HMASK;
            }
        }
    }

    out[gpos] = (float)(rank + 1 + base);

    // ---- tail: reset barrier counters for the next graph replay ----
    __syncthreads();
    if (t == 0) {
        unsigned int old = atomicAdd(&g_bar2, 1u);
        if (old == NBLK - 1u) {
            // every block has passed the g_bar1 spin; safe to reset both
            g_bar1 = 0u;
            g_bar2 = 0u;
        }
    }
}

extern "C" void kernel_launch(void* const* d_in, const int* in_sizes, int n_in,
                              void* d_out, int out_size) {
    (void)in_sizes; (void)n_in; (void)out_size;
    const int* x = (const int*)d_in[0];
    float* out = (float*)d_out;
    fused_counts_kernel<<<NBLK, LL>>>(x, out);
}

// round 4
// speedup vs baseline: 1.2076x; 1.2076x over previous
#include <cuda_runtime.h>

// PrefixSumCounts: counts[b,s] = #{t <= s : x[b,t] == x[b,s]}
// B=4, S=4096, V=32000 (fixed by this problem instance).
//
// Single fused kernel, 64 blocks = B*C chunks of 256.
//  phase 1: within-chunk inclusive rank = LDS scan over earlier warps +
//           __match_any_sync within warp. Per-chunk compact hash (1024 slots,
//           alpha<=0.25) of (value -> count); one insert per warp-distinct
//           value. Dump ALL slots packed ((v+1)<<9 | cnt) to global ->
//           table fully overwritten each launch (no pre-zero, L2-resident).
//  ONE grid barrier (arrive counter + separate monotonic release word).
//  phase 2: breadth-first batched probing of <=15 earlier-chunk tables:
//           each round issues up to 15 INDEPENDENT L2 loads (MLP), resolves,
//           repeats. alpha<=0.25 -> ~1.4 probes/chain -> 2-3 rounds.

#define BB 4
#define SS 4096
#define CC 16
#define LL 256              // SS / CC
#define NBLK (BB * CC)      // 64
#define HSLOTS 1024         // per-chunk hash slots, alpha <= 0.25
#define HMASK (HSLOTS - 1)

__device__ int g_tab[NBLK * HSLOTS];         // 256 KB; fully overwritten each launch
__device__ unsigned int g_arrive;            // 0 at load; reset by last arriver
__device__ unsigned int g_pad[31];           // keep release on a different line
__device__ unsigned int g_release;           // monotonic across launches

__device__ __forceinline__ unsigned int hash_v(int v) {
    return ((unsigned int)v * 2654435761u) >> 22;  // top 10 bits; caller masks
}

__global__ void __launch_bounds__(LL, 1) fused_counts_kernel(
    const int* __restrict__ x, float* __restrict__ out)
{
    __shared__ int xs[LL];
    __shared__ int sval[HSLOTS];
    __shared__ int scnt[HSLOTS];

    const int c = blockIdx.x & (CC - 1);
    const int b = blockIdx.x >> 4;
    const int t = threadIdx.x;
    const int w = t >> 5;
    const int lane = t & 31;
    const int gpos = b * SS + c * LL + t;

    // Snapshot release BEFORE this block arrives (only bumps after ALL arrive).
    unsigned int r0 = 0;
    if (t == 0) r0 = *(volatile unsigned int*)&g_release;

    // zero SMEM hash (4 slots per thread each array)
#pragma unroll
    for (int i = 0; i < HSLOTS / LL; ++i) {
        sval[t + i * LL] = 0;
        scnt[t + i * LL] = 0;
    }

    const int v = __ldg(&x[gpos]);
    xs[t] = v;
    __syncthreads();

    // ---- phase 1a: inclusive-rank = earlier-warp LDS scan + in-warp match ----
    int rank = 0;
    const int lim = w << 5;            // uniform per warp -> no divergence
    for (int j = 0; j < lim; ++j) {
        rank += (xs[j] == v);
    }
    const unsigned int mmask = __match_any_sync(0xffffffffu, v);
    rank += __popc(mmask & ((1u << lane) - 1u));

    // ---- phase 1b: hash insert, one op per warp-distinct value ----
    const int key = v + 1;
    if (lane == (__ffs(mmask) - 1)) {
        const int wcnt = __popc(mmask);
        unsigned int h = hash_v(v) & HMASK;
        while (true) {
            int old = atomicCAS(&sval[h], 0, key);
            if (old == 0 || old == key) { atomicAdd(&scnt[h], wcnt); break; }
            h = (h + 1) & HMASK;
        }
    }
    __syncthreads();

    // ---- phase 1c: dump packed table (all slots -> fully overwritten) ----
    int* my_tab = &g_tab[blockIdx.x * HSLOTS];
#pragma unroll
    for (int i = 0; i < HSLOTS / LL; ++i) {
        const int s = t + i * LL;
        const int k = sval[s];
        my_tab[s] = k ? ((k << 9) | scnt[s]) : 0;
    }

    // ---- grid barrier: dumps visible everywhere ----
    __syncthreads();
    if (t == 0) {
        __threadfence();
        unsigned int old = atomicAdd(&g_arrive, 1u);
        if (old == NBLK - 1u) {
            g_arrive = 0u;                 // safe: no one touches it until next launch
            __threadfence();
            atomicAdd(&g_release, 1u);     // single write to the spin word
        } else {
            volatile unsigned int* p = &g_release;
            while (*p == r0) { }
        }
        __threadfence();
    }
    __syncthreads();

    // ---- phase 2: breadth-first batched probing (independent loads/round) ----
    const unsigned int h0 = hash_v(v) & HMASK;
    const int* row = &g_tab[(b * CC) * HSLOTS];
    int base = 0;

    bool pend[CC - 1];
    unsigned int hh[CC - 1];
#pragma unroll
    for (int cp = 0; cp < CC - 1; ++cp) { pend[cp] = (cp < c); hh[cp] = h0; }

#pragma unroll
    for (int r = 0; r < 3; ++r) {
        int e[CC - 1];
#pragma unroll
        for (int cp = 0; cp < CC - 1; ++cp) {
            if (pend[cp]) e[cp] = __ldcg(&row[cp * HSLOTS + hh[cp]]);
        }
#pragma unroll
        for (int cp = 0; cp < CC - 1; ++cp) {
            if (pend[cp]) {
                const int ee = e[cp];
                if ((ee >> 9) == key) { base += (ee & 511); pend[cp] = false; }
                else if (ee == 0)     { pend[cp] = false; }
                else                  { hh[cp] = (hh[cp] + 1) & HMASK; }
            }
        }
    }
    // rare fallback for chains unresolved after 3 rounds
#pragma unroll
    for (int cp = 0; cp < CC - 1; ++cp) {
        while (pend[cp]) {
            const int ee = __ldcg(&row[cp * HSLOTS + hh[cp]]);
            if ((ee >> 9) == key) { base += (ee & 511); pend[cp] = false; }
            else if (ee == 0)     { pend[cp] = false; }
            else                  { hh[cp] = (hh[cp] + 1) & HMASK; }
        }
    }

    out[gpos] = (float)(rank + 1 + base);
}

extern "C" void kernel_launch(void* const* d_in, const int* in_sizes, int n_in,
                              void* d_out, int out_size) {
    (void)in_sizes; (void)n_in; (void)out_size;
    const int* x = (const int*)d_in[0];
    float* out = (float*)d_out;
    fused_counts_kernel<<<NBLK, LL>>>(x, out);
}